// round 12
// baseline (speedup 1.0000x reference)
#include <cuda_runtime.h>
#include <cuda_bf16.h>
#include <cstdint>

#define WARPS   13
#define THREADS (WARPS * 32)
#define N_UNITS 16384     // 4096 tiles * 4 factors

// smem byte layout
#define S_W1   0                          // 16KB: W1 bf16 [k=128][n=64], swizzled
#define S_XH   16384                      // 13 warps x 8KB: h fp32 stage -> X bf16 tile (in place)
#define S_T    (S_XH + WARPS*8192)        // 13 warps x 8KB: t fp32 [32][64], float4-slot swizzle
#define S_WGT  (S_T + WARPS*8192)         // 13 warps x 32 floats (16B aligned)
#define S_PAR  (S_WGT + WARPS*128)        // 129 floats: b1[64], W2[64], b2
#define SMEM_BYTES (S_PAR + 640)

static __device__ __forceinline__ uint32_t smem_u32(const void* p) {
    uint32_t a;
    asm("{ .reg .u64 t; cvta.to.shared.u64 t, %1; cvt.u32.u64 %0, t; }" : "=r"(a) : "l"(p));
    return a;
}
static __device__ __forceinline__ uint32_t pack2(float lo, float hi) {
    uint32_t r;
    asm("cvt.rn.bf16x2.f32 %0, %1, %2;" : "=r"(r) : "f"(hi), "f"(lo));
    return r;
}
static __device__ __forceinline__ void cp_async16(uint32_t dst, const void* src) {
    asm volatile("cp.async.cg.shared.global [%0], [%1], 16;" :: "r"(dst), "l"(src) : "memory");
}

#define LDSM_X4(a0,a1,a2,a3,addr) \
    asm volatile("ldmatrix.sync.aligned.m8n8.x4.shared.b16 {%0,%1,%2,%3}, [%4];" \
        : "=r"(a0),"=r"(a1),"=r"(a2),"=r"(a3) : "r"(addr))
#define LDSM_X4T(b0,b1,b2,b3,addr) \
    asm volatile("ldmatrix.sync.aligned.m8n8.x4.trans.shared.b16 {%0,%1,%2,%3}, [%4];" \
        : "=r"(b0),"=r"(b1),"=r"(b2),"=r"(b3) : "r"(addr))
#define MMA16816(d,a0,a1,a2,a3,b0,b1) \
    asm volatile("mma.sync.aligned.m16n8k16.row.col.f32.bf16.bf16.f32 " \
        "{%0,%1,%2,%3}, {%4,%5,%6,%7}, {%8,%9}, {%0,%1,%2,%3};" \
        : "+f"((d)[0]),"+f"((d)[1]),"+f"((d)[2]),"+f"((d)[3]) \
        : "r"(a0),"r"(a1),"r"(a2),"r"(a3),"r"(b0),"r"(b1))

__global__ __launch_bounds__(THREADS, 1)
void kgat_occ13_kernel(const float* __restrict__ node_emb,
                       const float* __restrict__ W1,
                       const float* __restrict__ b1,
                       const float* __restrict__ W2,
                       const float* __restrict__ b2,
                       const int*   __restrict__ users,
                       const int*   __restrict__ items,
                       const int*   __restrict__ utri,
                       const int*   __restrict__ itri,
                       float*       __restrict__ out)
{
    extern __shared__ char smem[];
    const int tid  = threadIdx.x;
    const int wid  = tid >> 5;
    const int lane = tid & 31;
    const int g    = lane >> 2;     // 0..7
    const int tc   = lane & 3;      // 0..3

    // ---- one-time: W1 -> bf16 smem [kk][n], slot swizzle s' = (n>>3)^(kk&7) ----
    for (int i = tid; i < 8192; i += THREADS) {
        int kk = i >> 6, n = i & 63;
        uint32_t byte = (uint32_t)kk * 128u + ((((uint32_t)n >> 3) ^ ((uint32_t)kk & 7)) << 4)
                        + (((uint32_t)n & 7) << 1);
        *(__nv_bfloat16*)(smem + S_W1 + byte) = __float2bfloat16(W1[i]);
    }
    float* sp = (float*)(smem + S_PAR);
    for (int i = tid; i < 129; i += THREADS)
        sp[i] = (i < 64) ? b1[i] : (i < 128 ? W2[i - 64] : b2[0]);
    __syncthreads();

    const uint32_t sb  = smem_u32(smem);
    const uint32_t Wu  = sb + S_W1;
    const uint32_t XHu = sb + S_XH + (uint32_t)wid * 8192u;
    const uint32_t Tu  = sb + S_T  + (uint32_t)wid * 8192u;
    char*   XHc  = smem + S_XH + wid * 8192;
    float*  stw  = (float*)(smem + S_T + wid * 8192);
    float4* stw4 = (float4*)stw;
    float*  swgt = (float*)(smem + S_WGT) + wid * 32;
    float4* swgt4 = (float4*)swgt;
    const float* node_f = node_emb;
    const float b2v = sp[128];

    const int stride = gridDim.x * WARPS;
    const int u0 = blockIdx.x * WARPS + wid;

    auto load_idx = [&](int u, int& hi, int& ti) {
        const int tile  = u >> 2;
        const int tower = tile >> 11;
        const int b     = (tile >> 1) & 1023;
        const int layer = tile & 1;
        const int* tri  = tower ? itri : utri;
        hi = tri[((b * 3 + 0) * 2 + layer) * 32 + lane];
        ti = tri[((b * 3 + 2) * 2 + layer) * 32 + lane];
    };
    // h rows -> XH stage (slot c^(r&7)); t rows -> T (slot c^(r&15))
    auto issue_h = [&](int u, int hidx) {
        const int f = u & 3;
        #pragma unroll
        for (int i = 0; i < 16; ++i) {
            const int r = 2 * i + (lane >> 4);
            const int c = lane & 15;
            const int hi = __shfl_sync(0xffffffffu, hidx, r);
            cp_async16(XHu + (uint32_t)(r * 256) + (uint32_t)(((c ^ (r & 7)) & 15) << 4),
                       node_f + (((size_t)hi * 4 + f) << 6) + (c << 2));
        }
        asm volatile("cp.async.commit_group;" ::: "memory");
    };
    auto issue_t = [&](int u, int tidx) {
        const int f = u & 3;
        #pragma unroll
        for (int i = 0; i < 16; ++i) {
            const int r = 2 * i + (lane >> 4);
            const int c = lane & 15;
            const int ti = __shfl_sync(0xffffffffu, tidx, r);
            cp_async16(Tu + (uint32_t)((r * 16 + (c ^ (r & 15))) << 4),
                       node_f + (((size_t)ti * 4 + f) << 6) + (c << 2));
        }
        asm volatile("cp.async.commit_group;" ::: "memory");
    };

    // ---- prologue: gather unit u0 ----
    if (u0 < N_UNITS) {
        int hi, ti;
        load_idx(u0, hi, ti);
        issue_h(u0, hi);
        issue_t(u0, ti);
    }

    for (int u = u0; u < N_UNITS; u += stride) {
        const int un = u + stride;
        const bool has_next = (un < N_UNITS);
        int hidx_n = 0, tidx_n = 0;
        if (has_next) load_idx(un, hidx_n, tidx_n);

        const int tile  = u >> 2;
        const int f     = u & 3;
        const int tower = tile >> 11;
        const int b     = (tile >> 1) & 1023;
        const int layer = tile & 1;

        // ---- origin slice (exact copy), overlaps in-flight gathers ----
        if (layer == 0) {
            const int oidx = (tower ? items : users)[b];
            float* outp = out + ((size_t)(tower * 3) * 1024 + b) * 256 + f * 64;
            ((float2*)outp)[lane] =
                ((const float2*)(node_emb + ((size_t)oidx * 4 + f) * 64))[lane];
        }

        asm volatile("cp.async.wait_group 0;" ::: "memory");
        __syncwarp();

        // ---- in-place convert: fp32 stage -> bf16 X tile (4 rounds x 8 rows) ----
        #pragma unroll
        for (int R = 0; R < 4; ++R) {
            float4 hv[4], tv[4];
            #pragma unroll
            for (int q = 0; q < 4; ++q) {
                const int r = 8 * R + 2 * q + (lane >> 4);
                const int c = lane & 15;
                hv[q] = *(const float4*)(XHc + r * 256 + (((c ^ (r & 7)) & 15) << 4));
                tv[q] = stw4[r * 16 + (c ^ (r & 15))];
            }
            __syncwarp();
            #pragma unroll
            for (int q = 0; q < 4; ++q) {
                const int r = 8 * R + 2 * q + (lane >> 4);
                const int c = lane & 15;
                uint2 hp; hp.x = pack2(hv[q].x, hv[q].y); hp.y = pack2(hv[q].z, hv[q].w);
                uint2 tp; tp.x = pack2(tv[q].x, tv[q].y); tp.y = pack2(tv[q].z, tv[q].w);
                const uint32_t half = ((uint32_t)c & 1) << 3;
                *(uint2*)(XHc + r * 256 + ((((c >> 1)    ) ^ (r & 7)) << 4) + half) = hp;
                *(uint2*)(XHc + r * 256 + ((((c >> 1) + 8) ^ (r & 7)) << 4) + half) = tp;
            }
            __syncwarp();
        }

        // ---- GEMM: C[32][64] = X[32][128] @ W1[128][64], bf16 HMMA ----
        float acc[2][8][4];
        #pragma unroll
        for (int mt = 0; mt < 2; ++mt)
            #pragma unroll
            for (int nt = 0; nt < 8; ++nt)
                #pragma unroll
                for (int e = 0; e < 4; ++e) acc[mt][nt][e] = 0.f;

        #pragma unroll
        for (int ks = 0; ks < 8; ++ks) {
            uint32_t B0[8], B1[8];
            const int krow = ks * 16 + (lane & 15);
            const int nsel = lane >> 4;
            #pragma unroll
            for (int np = 0; np < 4; ++np) {
                const int ntx = np * 2 + nsel;
                const uint32_t baddr = Wu + (uint32_t)krow * 128u
                                       + ((((uint32_t)ntx) ^ ((uint32_t)krow & 7)) << 4);
                LDSM_X4T(B0[np * 2], B1[np * 2], B0[np * 2 + 1], B1[np * 2 + 1], baddr);
            }
            #pragma unroll
            for (int mt = 0; mt < 2; ++mt) {
                const int r = mt * 16 + (lane & 15);
                const uint32_t slot = (uint32_t)(2 * ks + (lane >> 4));
                const uint32_t aaddr = XHu + (uint32_t)r * 256u + ((slot ^ ((uint32_t)r & 7)) << 4);
                uint32_t a0, a1, a2, a3;
                LDSM_X4(a0, a1, a2, a3, aaddr);
                #pragma unroll
                for (int nt = 0; nt < 8; ++nt)
                    MMA16816(acc[mt][nt], a0, a1, a2, a3, B0[nt], B1[nt]);
            }
        }

        // ---- logits: relu(C + b1) . W2 + b2 (b1/W2 via smem broadcast) ----
        float p[4] = {0.f, 0.f, 0.f, 0.f};
        #pragma unroll
        for (int nt = 0; nt < 8; ++nt) {
            const int n0 = nt * 8 + tc * 2;
            const float b1a = sp[n0], b1b = sp[n0 + 1];
            const float w2a = sp[64 + n0], w2b = sp[64 + n0 + 1];
            p[0] += fmaxf(acc[0][nt][0] + b1a, 0.f) * w2a + fmaxf(acc[0][nt][1] + b1b, 0.f) * w2b;
            p[1] += fmaxf(acc[0][nt][2] + b1a, 0.f) * w2a + fmaxf(acc[0][nt][3] + b1b, 0.f) * w2b;
            p[2] += fmaxf(acc[1][nt][0] + b1a, 0.f) * w2a + fmaxf(acc[1][nt][1] + b1b, 0.f) * w2b;
            p[3] += fmaxf(acc[1][nt][2] + b1a, 0.f) * w2a + fmaxf(acc[1][nt][3] + b1b, 0.f) * w2b;
        }
        float lg[4];
        #pragma unroll
        for (int e = 0; e < 4; ++e) {
            float v = p[e];
            v += __shfl_xor_sync(0xffffffffu, v, 1);
            v += __shfl_xor_sync(0xffffffffu, v, 2);
            lg[e] = v + b2v;   // rows: g, g+8, 16+g, 24+g
        }

        // ---- X buffer is free now: issue next unit's h gather ----
        if (has_next) issue_h(un, hidx_n);

        // ---- softmax over the warp's 32 rows ----
        float m = fmaxf(fmaxf(lg[0], lg[1]), fmaxf(lg[2], lg[3]));
        #pragma unroll
        for (int o = 4; o <= 16; o <<= 1)
            m = fmaxf(m, __shfl_xor_sync(0xffffffffu, m, o));
        float e0 = __expf(lg[0] - m), e1 = __expf(lg[1] - m);
        float e2 = __expf(lg[2] - m), e3 = __expf(lg[3] - m);
        float s = e0 + e1 + e2 + e3;
        #pragma unroll
        for (int o = 4; o <= 16; o <<= 1)
            s += __shfl_xor_sync(0xffffffffu, s, o);
        const float rs = __frcp_rn(s);
        if (tc == 0) {
            swgt[g]      = e0 * rs;
            swgt[g + 8]  = e1 * rs;
            swgt[g + 16] = e2 * rs;
            swgt[g + 24] = e3 * rs;
        }
        __syncwarp();

        // ---- weighted sum of exact fp32 t over k; dims d = 2*lane, 2*lane+1 ----
        {
            const int d    = 2 * lane;           // even, 0..62
            const int slot = d >> 2;             // lane>>1
            const int off  = d & 3;              // 0 or 2
            float a0 = 0.f, a1 = 0.f;
            #pragma unroll
            for (int r4 = 0; r4 < 8; ++r4) {
                const float4 w4 = swgt4[r4];
                #pragma unroll
                for (int j = 0; j < 4; ++j) {
                    const int rr = r4 * 4 + j;
                    const float w = (j == 0) ? w4.x : (j == 1) ? w4.y : (j == 2) ? w4.z : w4.w;
                    const float2 tv = *(const float2*)&stw[rr * 64 + ((slot ^ (rr & 15)) << 2) + off];
                    a0 += w * tv.x;
                    a1 += w * tv.y;
                }
            }
            float* outp = out + (((size_t)(tower * 3 + 1 + layer)) * 1024 + b) * 256 + f * 64;
            *(float2*)(outp + d) = make_float2(a0, a1);
        }
        __syncwarp();

        // ---- T buffer free: issue next unit's t gather ----
        if (has_next) issue_t(un, tidx_n);
    }
}

extern "C" void kernel_launch(void* const* d_in, const int* in_sizes, int n_in,
                              void* d_out, int out_size)
{
    const float* node_emb = (const float*)d_in[0];
    // d_in[1] = relation_emb: unused by the reference computation
    const float* W1    = (const float*)d_in[2];
    const float* b1    = (const float*)d_in[3];
    const float* W2    = (const float*)d_in[4];
    const float* b2    = (const float*)d_in[5];
    const int*   users = (const int*)d_in[6];
    const int*   items = (const int*)d_in[7];
    const int*   utri  = (const int*)d_in[8];
    const int*   itri  = (const int*)d_in[9];
    float*       out   = (float*)d_out;

    int nsm = 148;
    cudaDeviceGetAttribute(&nsm, cudaDevAttrMultiProcessorCount, 0);

    cudaFuncSetAttribute(kgat_occ13_kernel,
                         cudaFuncAttributeMaxDynamicSharedMemorySize, SMEM_BYTES);
    kgat_occ13_kernel<<<nsm, THREADS, SMEM_BYTES>>>(
        node_emb, W1, b1, W2, b2, users, items, utri, itri, out);
}

// round 13
// speedup vs baseline: 1.3029x; 1.3029x over previous
#include <cuda_runtime.h>
#include <cuda_bf16.h>
#include <cstdint>

#define WARPS   12
#define THREADS (WARPS * 32)
#define N_UNITS 16384     // 4096 tiles * 4 factors

// smem byte layout
#define S_W1   0                          // 16KB: W1 bf16 [k=128][n=64], swizzled
#define S_XH   16384                      // 12 warps x 8KB: h fp32 stage -> X bf16 tile (in place)
#define S_T    (S_XH + WARPS*8192)        // 12 warps x 8KB: t fp32 [32][64], float4-slot swizzle
#define S_WGT  (S_T + WARPS*8192)         // 12 warps x 32 floats (16B aligned)
#define S_PAR  (S_WGT + WARPS*128)        // 129 floats: b1[64], W2[64], b2
#define SMEM_BYTES (S_PAR + 640)

static __device__ __forceinline__ uint32_t smem_u32(const void* p) {
    uint32_t a;
    asm("{ .reg .u64 t; cvta.to.shared.u64 t, %1; cvt.u32.u64 %0, t; }" : "=r"(a) : "l"(p));
    return a;
}
static __device__ __forceinline__ uint32_t pack2(float lo, float hi) {
    uint32_t r;
    asm("cvt.rn.bf16x2.f32 %0, %1, %2;" : "=r"(r) : "f"(hi), "f"(lo));
    return r;
}
static __device__ __forceinline__ void cp_async16(uint32_t dst, const void* src) {
    asm volatile("cp.async.cg.shared.global [%0], [%1], 16;" :: "r"(dst), "l"(src) : "memory");
}

#define LDSM_X4(a0,a1,a2,a3,addr) \
    asm volatile("ldmatrix.sync.aligned.m8n8.x4.shared.b16 {%0,%1,%2,%3}, [%4];" \
        : "=r"(a0),"=r"(a1),"=r"(a2),"=r"(a3) : "r"(addr))
#define LDSM_X4T(b0,b1,b2,b3,addr) \
    asm volatile("ldmatrix.sync.aligned.m8n8.x4.trans.shared.b16 {%0,%1,%2,%3}, [%4];" \
        : "=r"(b0),"=r"(b1),"=r"(b2),"=r"(b3) : "r"(addr))
#define MMA16816(d,a0,a1,a2,a3,b0,b1) \
    asm volatile("mma.sync.aligned.m16n8k16.row.col.f32.bf16.bf16.f32 " \
        "{%0,%1,%2,%3}, {%4,%5,%6,%7}, {%8,%9}, {%0,%1,%2,%3};" \
        : "+f"((d)[0]),"+f"((d)[1]),"+f"((d)[2]),"+f"((d)[3]) \
        : "r"(a0),"r"(a1),"r"(a2),"r"(a3),"r"(b0),"r"(b1))

__global__ __launch_bounds__(THREADS, 1)
void kgat_occ_kernel(const float* __restrict__ node_emb,
                     const float* __restrict__ W1,
                     const float* __restrict__ b1,
                     const float* __restrict__ W2,
                     const float* __restrict__ b2,
                     const int*   __restrict__ users,
                     const int*   __restrict__ items,
                     const int*   __restrict__ utri,
                     const int*   __restrict__ itri,
                     float*       __restrict__ out)
{
    extern __shared__ char smem[];
    const int tid  = threadIdx.x;
    const int wid  = tid >> 5;
    const int lane = tid & 31;
    const int g    = lane >> 2;     // 0..7
    const int tc   = lane & 3;      // 0..3

    // ---- one-time: W1 -> bf16 smem [kk][n], slot swizzle s' = (n>>3)^(kk&7) ----
    for (int i = tid; i < 8192; i += THREADS) {
        int kk = i >> 6, n = i & 63;
        uint32_t byte = (uint32_t)kk * 128u + ((((uint32_t)n >> 3) ^ ((uint32_t)kk & 7)) << 4)
                        + (((uint32_t)n & 7) << 1);
        *(__nv_bfloat16*)(smem + S_W1 + byte) = __float2bfloat16(W1[i]);
    }
    float* sp = (float*)(smem + S_PAR);
    for (int i = tid; i < 129; i += THREADS)
        sp[i] = (i < 64) ? b1[i] : (i < 128 ? W2[i - 64] : b2[0]);
    __syncthreads();

    const uint32_t sb  = smem_u32(smem);
    const uint32_t Wu  = sb + S_W1;
    const uint32_t XHu = sb + S_XH + (uint32_t)wid * 8192u;
    const uint32_t Tu  = sb + S_T  + (uint32_t)wid * 8192u;
    char*   XHc  = smem + S_XH + wid * 8192;
    float*  stw  = (float*)(smem + S_T + wid * 8192);
    float4* stw4 = (float4*)stw;
    float*  swgt = (float*)(smem + S_WGT) + wid * 32;
    float4* swgt4 = (float4*)swgt;
    const float* node_f = node_emb;
    const float b2v = sp[128];

    const int stride = gridDim.x * WARPS;
    const int u0 = blockIdx.x * WARPS + wid;

    auto load_idx = [&](int u, int& hi, int& ti) {
        const int tile  = u >> 2;
        const int tower = tile >> 11;
        const int b     = (tile >> 1) & 1023;
        const int layer = tile & 1;
        const int* tri  = tower ? itri : utri;
        hi = tri[((b * 3 + 0) * 2 + layer) * 32 + lane];
        ti = tri[((b * 3 + 2) * 2 + layer) * 32 + lane];
    };
    // h rows -> XH stage (slot c^(r&7)); t rows -> T (slot c^(r&15))
    auto issue_h = [&](int u, int hidx) {
        const int f = u & 3;
        #pragma unroll
        for (int i = 0; i < 16; ++i) {
            const int r = 2 * i + (lane >> 4);
            const int c = lane & 15;
            const int hi = __shfl_sync(0xffffffffu, hidx, r);
            cp_async16(XHu + (uint32_t)(r * 256) + (uint32_t)(((c ^ (r & 7)) & 15) << 4),
                       node_f + (((size_t)hi * 4 + f) << 6) + (c << 2));
        }
        asm volatile("cp.async.commit_group;" ::: "memory");
    };
    auto issue_t = [&](int u, int tidx) {
        const int f = u & 3;
        #pragma unroll
        for (int i = 0; i < 16; ++i) {
            const int r = 2 * i + (lane >> 4);
            const int c = lane & 15;
            const int ti = __shfl_sync(0xffffffffu, tidx, r);
            cp_async16(Tu + (uint32_t)((r * 16 + (c ^ (r & 15))) << 4),
                       node_f + (((size_t)ti * 4 + f) << 6) + (c << 2));
        }
        asm volatile("cp.async.commit_group;" ::: "memory");
    };

    // ---- prologue: gather unit u0 ----
    if (u0 < N_UNITS) {
        int hi, ti;
        load_idx(u0, hi, ti);
        issue_h(u0, hi);
        issue_t(u0, ti);
    }

    for (int u = u0; u < N_UNITS; u += stride) {
        const int un = u + stride;
        const bool has_next = (un < N_UNITS);
        int hidx_n = 0, tidx_n = 0;
        if (has_next) load_idx(un, hidx_n, tidx_n);

        const int tile  = u >> 2;
        const int f     = u & 3;
        const int tower = tile >> 11;
        const int b     = (tile >> 1) & 1023;
        const int layer = tile & 1;

        // ---- origin slice (exact copy), overlaps in-flight gathers ----
        if (layer == 0) {
            const int oidx = (tower ? items : users)[b];
            float* outp = out + ((size_t)(tower * 3) * 1024 + b) * 256 + f * 64;
            ((float2*)outp)[lane] =
                ((const float2*)(node_emb + ((size_t)oidx * 4 + f) * 64))[lane];
        }

        asm volatile("cp.async.wait_group 0;" ::: "memory");
        __syncwarp();

        // ---- in-place convert: fp32 stage -> bf16 X tile (4 rounds x 8 rows) ----
        #pragma unroll
        for (int R = 0; R < 4; ++R) {
            float4 hv[4], tv[4];
            #pragma unroll
            for (int q = 0; q < 4; ++q) {
                const int r = 8 * R + 2 * q + (lane >> 4);
                const int c = lane & 15;
                hv[q] = *(const float4*)(XHc + r * 256 + (((c ^ (r & 7)) & 15) << 4));
                tv[q] = stw4[r * 16 + (c ^ (r & 15))];
            }
            __syncwarp();
            #pragma unroll
            for (int q = 0; q < 4; ++q) {
                const int r = 8 * R + 2 * q + (lane >> 4);
                const int c = lane & 15;
                uint2 hp; hp.x = pack2(hv[q].x, hv[q].y); hp.y = pack2(hv[q].z, hv[q].w);
                uint2 tp; tp.x = pack2(tv[q].x, tv[q].y); tp.y = pack2(tv[q].z, tv[q].w);
                const uint32_t half = ((uint32_t)c & 1) << 3;
                *(uint2*)(XHc + r * 256 + ((((c >> 1)    ) ^ (r & 7)) << 4) + half) = hp;
                *(uint2*)(XHc + r * 256 + ((((c >> 1) + 8) ^ (r & 7)) << 4) + half) = tp;
            }
            __syncwarp();
        }

        // ---- GEMM: C[32][64] = X[32][128] @ W1[128][64], bf16 HMMA ----
        float acc[2][8][4];
        #pragma unroll
        for (int mt = 0; mt < 2; ++mt)
            #pragma unroll
            for (int nt = 0; nt < 8; ++nt)
                #pragma unroll
                for (int e = 0; e < 4; ++e) acc[mt][nt][e] = 0.f;

        #pragma unroll
        for (int ks = 0; ks < 8; ++ks) {
            uint32_t B0[8], B1[8];
            const int krow = ks * 16 + (lane & 15);
            const int nsel = lane >> 4;
            #pragma unroll
            for (int np = 0; np < 4; ++np) {
                const int ntx = np * 2 + nsel;
                const uint32_t baddr = Wu + (uint32_t)krow * 128u
                                       + ((((uint32_t)ntx) ^ ((uint32_t)krow & 7)) << 4);
                LDSM_X4T(B0[np * 2], B1[np * 2], B0[np * 2 + 1], B1[np * 2 + 1], baddr);
            }
            #pragma unroll
            for (int mt = 0; mt < 2; ++mt) {
                const int r = mt * 16 + (lane & 15);
                const uint32_t slot = (uint32_t)(2 * ks + (lane >> 4));
                const uint32_t aaddr = XHu + (uint32_t)r * 256u + ((slot ^ ((uint32_t)r & 7)) << 4);
                uint32_t a0, a1, a2, a3;
                LDSM_X4(a0, a1, a2, a3, aaddr);
                #pragma unroll
                for (int nt = 0; nt < 8; ++nt)
                    MMA16816(acc[mt][nt], a0, a1, a2, a3, B0[nt], B1[nt]);
            }
        }

        // ---- logits: relu(C + b1) . W2 + b2 (b1/W2 via smem broadcast) ----
        float p[4] = {0.f, 0.f, 0.f, 0.f};
        #pragma unroll
        for (int nt = 0; nt < 8; ++nt) {
            const int n0 = nt * 8 + tc * 2;
            const float b1a = sp[n0], b1b = sp[n0 + 1];
            const float w2a = sp[64 + n0], w2b = sp[64 + n0 + 1];
            p[0] += fmaxf(acc[0][nt][0] + b1a, 0.f) * w2a + fmaxf(acc[0][nt][1] + b1b, 0.f) * w2b;
            p[1] += fmaxf(acc[0][nt][2] + b1a, 0.f) * w2a + fmaxf(acc[0][nt][3] + b1b, 0.f) * w2b;
            p[2] += fmaxf(acc[1][nt][0] + b1a, 0.f) * w2a + fmaxf(acc[1][nt][1] + b1b, 0.f) * w2b;
            p[3] += fmaxf(acc[1][nt][2] + b1a, 0.f) * w2a + fmaxf(acc[1][nt][3] + b1b, 0.f) * w2b;
        }
        float lg[4];
        #pragma unroll
        for (int e = 0; e < 4; ++e) {
            float v = p[e];
            v += __shfl_xor_sync(0xffffffffu, v, 1);
            v += __shfl_xor_sync(0xffffffffu, v, 2);
            lg[e] = v + b2v;   // rows: g, g+8, 16+g, 24+g
        }

        // ---- X buffer is free now: issue next unit's h gather ----
        if (has_next) issue_h(un, hidx_n);

        // ---- softmax over the warp's 32 rows ----
        float m = fmaxf(fmaxf(lg[0], lg[1]), fmaxf(lg[2], lg[3]));
        #pragma unroll
        for (int o = 4; o <= 16; o <<= 1)
            m = fmaxf(m, __shfl_xor_sync(0xffffffffu, m, o));
        float e0 = __expf(lg[0] - m), e1 = __expf(lg[1] - m);
        float e2 = __expf(lg[2] - m), e3 = __expf(lg[3] - m);
        float s = e0 + e1 + e2 + e3;
        #pragma unroll
        for (int o = 4; o <= 16; o <<= 1)
            s += __shfl_xor_sync(0xffffffffu, s, o);
        const float rs = __frcp_rn(s);
        if (tc == 0) {
            swgt[g]      = e0 * rs;
            swgt[g + 8]  = e1 * rs;
            swgt[g + 16] = e2 * rs;
            swgt[g + 24] = e3 * rs;
        }
        __syncwarp();

        // ---- weighted sum of exact fp32 t over k; dims d = 2*lane, 2*lane+1 ----
        {
            const int slot = lane >> 1;          // (2*lane)>>2
            const int off  = (lane & 1) << 1;    // 0 or 2
            float a0 = 0.f, a1 = 0.f;
            #pragma unroll
            for (int r4 = 0; r4 < 8; ++r4) {
                const float4 w4 = swgt4[r4];
                #pragma unroll
                for (int j = 0; j < 4; ++j) {
                    const int rr = r4 * 4 + j;
                    const float w = (j == 0) ? w4.x : (j == 1) ? w4.y : (j == 2) ? w4.z : w4.w;
                    const float2 tv = *(const float2*)&stw[rr * 64 + ((slot ^ (rr & 15)) << 2) + off];
                    a0 += w * tv.x;
                    a1 += w * tv.y;
                }
            }
            float* outp = out + (((size_t)(tower * 3 + 1 + layer)) * 1024 + b) * 256 + f * 64;
            *(float2*)(outp + 2 * lane) = make_float2(a0, a1);
        }
        __syncwarp();

        // ---- T buffer free: issue next unit's t gather ----
        if (has_next) issue_t(un, tidx_n);
    }
}

extern "C" void kernel_launch(void* const* d_in, const int* in_sizes, int n_in,
                              void* d_out, int out_size)
{
    const float* node_emb = (const float*)d_in[0];
    // d_in[1] = relation_emb: unused by the reference computation
    const float* W1    = (const float*)d_in[2];
    const float* b1    = (const float*)d_in[3];
    const float* W2    = (const float*)d_in[4];
    const float* b2    = (const float*)d_in[5];
    const int*   users = (const int*)d_in[6];
    const int*   items = (const int*)d_in[7];
    const int*   utri  = (const int*)d_in[8];
    const int*   itri  = (const int*)d_in[9];
    float*       out   = (float*)d_out;

    int nsm = 148;
    cudaDeviceGetAttribute(&nsm, cudaDevAttrMultiProcessorCount, 0);

    cudaFuncSetAttribute(kgat_occ_kernel,
                         cudaFuncAttributeMaxDynamicSharedMemorySize, SMEM_BYTES);
    kgat_occ_kernel<<<nsm, THREADS, SMEM_BYTES>>>(
        node_emb, W1, b1, W2, b2, users, items, utri, itri, out);
}

// round 14
// speedup vs baseline: 1.3353x; 1.0249x over previous
#include <cuda_runtime.h>
#include <cuda_bf16.h>
#include <cstdint>

#define WARPS   12
#define THREADS (WARPS * 32)
#define N_UNITS 16384     // 4096 tiles * 4 factors

// smem byte layout
#define S_W1   0                          // 16KB: W1 bf16 [k=128][n=64], swizzled
#define S_H    16384                      // 12 warps x 8KB: h fp32 [32][64], float4-slot swizzle
#define S_T    (S_H + WARPS*8192)         // 12 warps x 8KB: t fp32 [32][64], float4-slot swizzle
#define S_WGT  (S_T + WARPS*8192)         // 12 warps x 32 floats (16B aligned)
#define S_PAR  (S_WGT + WARPS*128)        // 129 floats: b1[64], W2[64], b2
#define SMEM_BYTES (S_PAR + 640)

static __device__ __forceinline__ uint32_t smem_u32(const void* p) {
    uint32_t a;
    asm("{ .reg .u64 t; cvta.to.shared.u64 t, %1; cvt.u32.u64 %0, t; }" : "=r"(a) : "l"(p));
    return a;
}
static __device__ __forceinline__ uint32_t pack2(float lo, float hi) {
    uint32_t r;
    asm("cvt.rn.bf16x2.f32 %0, %1, %2;" : "=r"(r) : "f"(hi), "f"(lo));
    return r;
}
static __device__ __forceinline__ void cp_async16(uint32_t dst, const void* src) {
    asm volatile("cp.async.cg.shared.global [%0], [%1], 16;" :: "r"(dst), "l"(src) : "memory");
}

#define LDS64F(f0,f1,addr) \
    asm volatile("ld.shared.v2.f32 {%0,%1}, [%2];" : "=f"(f0),"=f"(f1) : "r"(addr))
#define LDSM_X4T(b0,b1,b2,b3,addr) \
    asm volatile("ldmatrix.sync.aligned.m8n8.x4.trans.shared.b16 {%0,%1,%2,%3}, [%4];" \
        : "=r"(b0),"=r"(b1),"=r"(b2),"=r"(b3) : "r"(addr))
#define MMA16816(d,a0,a1,a2,a3,b0,b1) \
    asm volatile("mma.sync.aligned.m16n8k16.row.col.f32.bf16.bf16.f32 " \
        "{%0,%1,%2,%3}, {%4,%5,%6,%7}, {%8,%9}, {%0,%1,%2,%3};" \
        : "+f"((d)[0]),"+f"((d)[1]),"+f"((d)[2]),"+f"((d)[3]) \
        : "r"(a0),"r"(a1),"r"(a2),"r"(a3),"r"(b0),"r"(b1))

__global__ __launch_bounds__(THREADS, 1)
void kgat_nofuse_kernel(const float* __restrict__ node_emb,
                        const float* __restrict__ W1,
                        const float* __restrict__ b1,
                        const float* __restrict__ W2,
                        const float* __restrict__ b2,
                        const int*   __restrict__ users,
                        const int*   __restrict__ items,
                        const int*   __restrict__ utri,
                        const int*   __restrict__ itri,
                        float*       __restrict__ out)
{
    extern __shared__ char smem[];
    const int tid  = threadIdx.x;
    const int wid  = tid >> 5;
    const int lane = tid & 31;
    const int g    = lane >> 2;     // 0..7
    const int tc   = lane & 3;      // 0..3

    // ---- one-time: W1 -> bf16 smem [kk][n], slot swizzle s' = (n>>3)^(kk&7) ----
    for (int i = tid; i < 8192; i += THREADS) {
        int kk = i >> 6, n = i & 63;
        uint32_t byte = (uint32_t)kk * 128u + ((((uint32_t)n >> 3) ^ ((uint32_t)kk & 7)) << 4)
                        + (((uint32_t)n & 7) << 1);
        *(__nv_bfloat16*)(smem + S_W1 + byte) = __float2bfloat16(W1[i]);
    }
    float* sp = (float*)(smem + S_PAR);
    for (int i = tid; i < 129; i += THREADS)
        sp[i] = (i < 64) ? b1[i] : (i < 128 ? W2[i - 64] : b2[0]);
    __syncthreads();

    const uint32_t sb = smem_u32(smem);
    const uint32_t Wu = sb + S_W1;
    const uint32_t Hu = sb + S_H + (uint32_t)wid * 8192u;
    const uint32_t Tu = sb + S_T + (uint32_t)wid * 8192u;
    float*  stw   = (float*)(smem + S_T + wid * 8192);
    float*  swgt  = (float*)(smem + S_WGT) + wid * 32;
    float4* swgt4 = (float4*)swgt;
    const float* node_f = node_emb;
    const float b2v = sp[128];

    // ---- A-fragment address constants (per thread) ----
    // addr(r, q) = buf + r*256 + (((q>>2) ^ (r&15))<<4) + ((q&3)<<2)
    // decomposed: BH/BT + mt*4096 + a1*2048 + ((kk>>1)^a1)<<7 + y[a2][kk&1]
    const uint32_t x1   = (uint32_t)((lane >> 3) & 1) << 5;
    const uint32_t x2   = (uint32_t)((lane >> 4) & 1) << 6;
    const uint32_t y00  = x1 + x2;
    const uint32_t y01  = x1 + 64 - x2;
    const uint32_t y10  = 32 - x1 + x2;
    const uint32_t y11  = 96 - x1 - x2;
    const uint32_t aoff = (uint32_t)g * 256u
                        + (uint32_t)((((tc >> 1) ^ (g & 1)) & 1) << 4)
                        + (uint32_t)((tc & 1) << 3);
    const uint32_t BH = Hu + aoff;
    const uint32_t BT = Tu + aoff;

    const int stride = gridDim.x * WARPS;
    const int u0 = blockIdx.x * WARPS + wid;

    auto load_idx = [&](int u, int& hi, int& ti) {
        const int tile  = u >> 2;
        const int tower = tile >> 11;
        const int b     = (tile >> 1) & 1023;
        const int layer = tile & 1;
        const int* tri  = tower ? itri : utri;
        hi = tri[((b * 3 + 0) * 2 + layer) * 32 + lane];
        ti = tri[((b * 3 + 2) * 2 + layer) * 32 + lane];
    };
    // rows -> buffer with float4-slot swizzle slot' = c ^ (r&15)
    auto issue_g = [&](int u, int idx, uint32_t buf) {
        const int f = u & 3;
        #pragma unroll
        for (int i = 0; i < 16; ++i) {
            const int r = 2 * i + (lane >> 4);
            const int c = lane & 15;
            const int nid = __shfl_sync(0xffffffffu, idx, r);
            cp_async16(buf + (uint32_t)((r * 16 + (c ^ (r & 15))) << 4),
                       node_f + (((size_t)nid * 4 + f) << 6) + (c << 2));
        }
        asm volatile("cp.async.commit_group;" ::: "memory");
    };

    // ---- prologue: gather unit u0 ----
    if (u0 < N_UNITS) {
        int hi, ti;
        load_idx(u0, hi, ti);
        issue_g(u0, hi, Hu);
        issue_g(u0, ti, Tu);
    }

    for (int u = u0; u < N_UNITS; u += stride) {
        const int un = u + stride;
        const bool has_next = (un < N_UNITS);
        int hidx_n = 0, tidx_n = 0;
        if (has_next) load_idx(un, hidx_n, tidx_n);

        const int tile  = u >> 2;
        const int f     = u & 3;
        const int tower = tile >> 11;
        const int b     = (tile >> 1) & 1023;
        const int layer = tile & 1;

        // ---- origin slice (exact copy), overlaps in-flight gathers ----
        if (layer == 0) {
            const int oidx = (tower ? items : users)[b];
            float* outp = out + ((size_t)(tower * 3) * 1024 + b) * 256 + f * 64;
            ((float2*)outp)[lane] =
                ((const float2*)(node_emb + ((size_t)oidx * 4 + f) * 64))[lane];
        }

        asm volatile("cp.async.wait_group 0;" ::: "memory");
        __syncwarp();

        // ---- GEMM: C[32][64] = [h|t][32][128] @ W1[128][64], bf16 HMMA,
        //      A fragments built on the fly from fp32 staging ----
        float acc[2][8][4];
        #pragma unroll
        for (int mt = 0; mt < 2; ++mt)
            #pragma unroll
            for (int nt = 0; nt < 8; ++nt)
                #pragma unroll
                for (int e = 0; e < 4; ++e) acc[mt][nt][e] = 0.f;

        #pragma unroll
        for (int ks = 0; ks < 8; ++ks) {
            // B fragments: 4 x ldmatrix.x4.trans covering 8 n-tiles
            uint32_t B0[8], B1[8];
            const int krow = ks * 16 + (lane & 15);
            const int nsel = lane >> 4;
            #pragma unroll
            for (int np = 0; np < 4; ++np) {
                const int ntx = np * 2 + nsel;
                const uint32_t baddr = Wu + (uint32_t)krow * 128u
                                       + ((((uint32_t)ntx) ^ ((uint32_t)krow & 7)) << 4);
                LDSM_X4T(B0[np * 2], B1[np * 2], B0[np * 2 + 1], B1[np * 2 + 1], baddr);
            }

            const int kk = ks & 3;
            const uint32_t bufb = (ks < 4) ? BH : BT;
            const uint32_t c3_0 = (uint32_t)(((kk >> 1) & 1)    ) << 7;  // a1 = 0
            const uint32_t c3_1 = (uint32_t)(((kk >> 1) & 1) ^ 1) << 7;  // a1 = 1
            const uint32_t ya   = (kk & 1) ? y01 : y00;                  // a2 = 0
            const uint32_t yb   = (kk & 1) ? y11 : y10;                  // a2 = 1

            #pragma unroll
            for (int mt = 0; mt < 2; ++mt) {
                const uint32_t mb = bufb + (uint32_t)mt * 4096u;
                float f0, f1;
                uint32_t a0, a1r, a2r, a3r;
                LDS64F(f0, f1, mb + ya + c3_0);              a0  = pack2(f0, f1);
                LDS64F(f0, f1, mb + 2048u + ya + c3_1);      a1r = pack2(f0, f1);
                LDS64F(f0, f1, mb + yb + c3_0);              a2r = pack2(f0, f1);
                LDS64F(f0, f1, mb + 2048u + yb + c3_1);      a3r = pack2(f0, f1);
                #pragma unroll
                for (int nt = 0; nt < 8; ++nt)
                    MMA16816(acc[mt][nt], a0, a1r, a2r, a3r, B0[nt], B1[nt]);
            }
        }

        // ---- logits: relu(C + b1) . W2 + b2 (b1/W2 via smem broadcast) ----
        float p[4] = {0.f, 0.f, 0.f, 0.f};
        #pragma unroll
        for (int nt = 0; nt < 8; ++nt) {
            const int n0 = nt * 8 + tc * 2;
            const float b1a = sp[n0], b1b = sp[n0 + 1];
            const float w2a = sp[64 + n0], w2b = sp[64 + n0 + 1];
            p[0] += fmaxf(acc[0][nt][0] + b1a, 0.f) * w2a + fmaxf(acc[0][nt][1] + b1b, 0.f) * w2b;
            p[1] += fmaxf(acc[0][nt][2] + b1a, 0.f) * w2a + fmaxf(acc[0][nt][3] + b1b, 0.f) * w2b;
            p[2] += fmaxf(acc[1][nt][0] + b1a, 0.f) * w2a + fmaxf(acc[1][nt][1] + b1b, 0.f) * w2b;
            p[3] += fmaxf(acc[1][nt][2] + b1a, 0.f) * w2a + fmaxf(acc[1][nt][3] + b1b, 0.f) * w2b;
        }
        float lg[4];
        #pragma unroll
        for (int e = 0; e < 4; ++e) {
            float v = p[e];
            v += __shfl_xor_sync(0xffffffffu, v, 1);
            v += __shfl_xor_sync(0xffffffffu, v, 2);
            lg[e] = v + b2v;   // rows: g, g+8, 16+g, 24+g
        }

        // ---- H buffer consumed (GEMM done): issue next unit's h gather ----
        if (has_next) issue_g(un, hidx_n, Hu);

        // ---- softmax over the warp's 32 rows ----
        float m = fmaxf(fmaxf(lg[0], lg[1]), fmaxf(lg[2], lg[3]));
        #pragma unroll
        for (int o = 4; o <= 16; o <<= 1)
            m = fmaxf(m, __shfl_xor_sync(0xffffffffu, m, o));
        float e0 = __expf(lg[0] - m), e1 = __expf(lg[1] - m);
        float e2 = __expf(lg[2] - m), e3 = __expf(lg[3] - m);
        float s = e0 + e1 + e2 + e3;
        #pragma unroll
        for (int o = 4; o <= 16; o <<= 1)
            s += __shfl_xor_sync(0xffffffffu, s, o);
        const float rs = __frcp_rn(s);
        if (tc == 0) {
            swgt[g]      = e0 * rs;
            swgt[g + 8]  = e1 * rs;
            swgt[g + 16] = e2 * rs;
            swgt[g + 24] = e3 * rs;
        }
        __syncwarp();

        // ---- weighted sum of exact fp32 t over k; dims d = 2*lane, 2*lane+1 ----
        {
            const int slot = lane >> 1;          // (2*lane)>>2
            const int off  = (lane & 1) << 1;    // 0 or 2
            float a0 = 0.f, a1 = 0.f;
            #pragma unroll
            for (int r4 = 0; r4 < 8; ++r4) {
                const float4 w4 = swgt4[r4];
                #pragma unroll
                for (int j = 0; j < 4; ++j) {
                    const int rr = r4 * 4 + j;
                    const float w = (j == 0) ? w4.x : (j == 1) ? w4.y : (j == 2) ? w4.z : w4.w;
                    const float2 tv = *(const float2*)&stw[rr * 64 + ((slot ^ (rr & 15)) << 2) + off];
                    a0 += w * tv.x;
                    a1 += w * tv.y;
                }
            }
            float* outp = out + (((size_t)(tower * 3 + 1 + layer)) * 1024 + b) * 256 + f * 64;
            *(float2*)(outp + 2 * lane) = make_float2(a0, a1);
        }
        __syncwarp();

        // ---- T buffer free: issue next unit's t gather ----
        if (has_next) issue_g(un, tidx_n, Tu);
    }
}

extern "C" void kernel_launch(void* const* d_in, const int* in_sizes, int n_in,
                              void* d_out, int out_size)
{
    const float* node_emb = (const float*)d_in[0];
    // d_in[1] = relation_emb: unused by the reference computation
    const float* W1    = (const float*)d_in[2];
    const float* b1    = (const float*)d_in[3];
    const float* W2    = (const float*)d_in[4];
    const float* b2    = (const float*)d_in[5];
    const int*   users = (const int*)d_in[6];
    const int*   items = (const int*)d_in[7];
    const int*   utri  = (const int*)d_in[8];
    const int*   itri  = (const int*)d_in[9];
    float*       out   = (float*)d_out;

    int nsm = 148;
    cudaDeviceGetAttribute(&nsm, cudaDevAttrMultiProcessorCount, 0);

    cudaFuncSetAttribute(kgat_nofuse_kernel,
                         cudaFuncAttributeMaxDynamicSharedMemorySize, SMEM_BYTES);
    kgat_nofuse_kernel<<<nsm, THREADS, SMEM_BYTES>>>(
        node_emb, W1, b1, W2, b2, users, items, utri, itri, out);
}

// round 16
// speedup vs baseline: 1.4096x; 1.0557x over previous
#include <cuda_runtime.h>
#include <cuda_bf16.h>
#include <cstdint>

#define WARPS   12
#define THREADS (WARPS * 32)
#define N_UNITS 16384     // 4096 tiles * 4 factors

// smem byte layout
#define S_W1   0                          // 16KB: W1 bf16 [k=128][n=64], swizzled
#define S_H    16384                      // 12 warps x 8KB: h fp32 [32][64], float4-slot swizzle
#define S_T    (S_H + WARPS*8192)         // 12 warps x 8KB: t fp32 [32][64], float4-slot swizzle
#define S_WGT  (S_T + WARPS*8192)         // 12 warps x 32 floats (16B aligned)
#define S_PAR  (S_WGT + WARPS*128)        // 129 floats: b1[64], W2[64], b2
#define SMEM_BYTES (S_PAR + 640)

static __device__ __forceinline__ uint32_t smem_u32(const void* p) {
    uint32_t a;
    asm("{ .reg .u64 t; cvta.to.shared.u64 t, %1; cvt.u32.u64 %0, t; }" : "=r"(a) : "l"(p));
    return a;
}
static __device__ __forceinline__ uint32_t pack2(float lo, float hi) {
    uint32_t r;
    asm("cvt.rn.bf16x2.f32 %0, %1, %2;" : "=r"(r) : "f"(hi), "f"(lo));
    return r;
}
static __device__ __forceinline__ void cp_async16(uint32_t dst, const void* src) {
    asm volatile("cp.async.cg.shared.global [%0], [%1], 16;" :: "r"(dst), "l"(src) : "memory");
}

#define LDS64F(f0,f1,addr) \
    asm volatile("ld.shared.v2.f32 {%0,%1}, [%2];" : "=f"(f0),"=f"(f1) : "r"(addr))
#define LDSM_X4T(b0,b1,b2,b3,addr) \
    asm volatile("ldmatrix.sync.aligned.m8n8.x4.trans.shared.b16 {%0,%1,%2,%3}, [%4];" \
        : "=r"(b0),"=r"(b1),"=r"(b2),"=r"(b3) : "r"(addr))
#define MMA16816(d,a0,a1,a2,a3,b0,b1) \
    asm volatile("mma.sync.aligned.m16n8k16.row.col.f32.bf16.bf16.f32 " \
        "{%0,%1,%2,%3}, {%4,%5,%6,%7}, {%8,%9}, {%0,%1,%2,%3};" \
        : "+f"((d)[0]),"+f"((d)[1]),"+f"((d)[2]),"+f"((d)[3]) \
        : "r"(a0),"r"(a1),"r"(a2),"r"(a3),"r"(b0),"r"(b1))

__global__ __launch_bounds__(THREADS, 1)
void kgat_split_kernel(const float* __restrict__ node_emb,
                       const float* __restrict__ W1,
                       const float* __restrict__ b1,
                       const float* __restrict__ W2,
                       const float* __restrict__ b2,
                       const int*   __restrict__ users,
                       const int*   __restrict__ items,
                       const int*   __restrict__ utri,
                       const int*   __restrict__ itri,
                       float*       __restrict__ out)
{
    extern __shared__ char smem[];
    const int tid  = threadIdx.x;
    const int wid  = tid >> 5;
    const int lane = tid & 31;
    const int g    = lane >> 2;     // 0..7
    const int tc   = lane & 3;      // 0..3

    // ---- one-time: W1 -> bf16 smem [kk][n], slot swizzle s' = (n>>3)^(kk&7) ----
    for (int i = tid; i < 8192; i += THREADS) {
        int kk = i >> 6, n = i & 63;
        uint32_t byte = (uint32_t)kk * 128u + ((((uint32_t)n >> 3) ^ ((uint32_t)kk & 7)) << 4)
                        + (((uint32_t)n & 7) << 1);
        *(__nv_bfloat16*)(smem + S_W1 + byte) = __float2bfloat16(W1[i]);
    }
    float* sp = (float*)(smem + S_PAR);
    for (int i = tid; i < 129; i += THREADS)
        sp[i] = (i < 64) ? b1[i] : (i < 128 ? W2[i - 64] : b2[0]);
    __syncthreads();

    const uint32_t sb = smem_u32(smem);
    const uint32_t Wu = sb + S_W1;
    const uint32_t Hu = sb + S_H + (uint32_t)wid * 8192u;
    const uint32_t Tu = sb + S_T + (uint32_t)wid * 8192u;
    float*  stw   = (float*)(smem + S_T + wid * 8192);
    float*  swgt  = (float*)(smem + S_WGT) + wid * 32;
    float4* swgt4 = (float4*)swgt;
    const float* node_f = node_emb;
    const float b2v = sp[128];

    // ---- A-fragment address constants (per thread) ----
    // addr(r, q) = buf + r*256 + (((q>>2) ^ (r&15))<<4) + ((q&3)<<2)
    const uint32_t x1   = (uint32_t)((lane >> 3) & 1) << 5;
    const uint32_t x2   = (uint32_t)((lane >> 4) & 1) << 6;
    const uint32_t y00  = x1 + x2;
    const uint32_t y01  = x1 + 64 - x2;
    const uint32_t y10  = 32 - x1 + x2;
    const uint32_t y11  = 96 - x1 - x2;
    const uint32_t aoff = (uint32_t)g * 256u
                        + (uint32_t)((((tc >> 1) ^ (g & 1)) & 1) << 4)
                        + (uint32_t)((tc & 1) << 3);
    const uint32_t BH = Hu + aoff;
    const uint32_t BT = Tu + aoff;

    const int stride = gridDim.x * WARPS;
    const int u0 = blockIdx.x * WARPS + wid;

    auto load_idx = [&](int u, int& hi, int& ti) {
        const int tile  = u >> 2;
        const int tower = tile >> 11;
        const int b     = (tile >> 1) & 1023;
        const int layer = tile & 1;
        const int* tri  = tower ? itri : utri;
        hi = tri[((b * 3 + 0) * 2 + layer) * 32 + lane];
        ti = tri[((b * 3 + 2) * 2 + layer) * 32 + lane];
    };
    // rows -> buffer with float4-slot swizzle slot' = c ^ (r&15); one commit group
    auto issue_g = [&](int u, int idx, uint32_t buf) {
        const int f = u & 3;
        #pragma unroll
        for (int i = 0; i < 16; ++i) {
            const int r = 2 * i + (lane >> 4);
            const int c = lane & 15;
            const int nid = __shfl_sync(0xffffffffu, idx, r);
            cp_async16(buf + (uint32_t)((r * 16 + (c ^ (r & 15))) << 4),
                       node_f + (((size_t)nid * 4 + f) << 6) + (c << 2));
        }
        asm volatile("cp.async.commit_group;" ::: "memory");
    };

    // one half-GEMM step: A fragments from fp32 staging at base bufb, B k-rows kbase+
    auto gemm_half = [&](float (*acc)[8][4], uint32_t bufb, int kbase) {
        #pragma unroll
        for (int ks = 0; ks < 4; ++ks) {
            uint32_t B0[8], B1[8];
            const int krow = kbase + ks * 16 + (lane & 15);
            const int nsel = lane >> 4;
            #pragma unroll
            for (int np = 0; np < 4; ++np) {
                const int ntx = np * 2 + nsel;
                const uint32_t baddr = Wu + (uint32_t)krow * 128u
                                       + ((((uint32_t)ntx) ^ ((uint32_t)krow & 7)) << 4);
                LDSM_X4T(B0[np * 2], B1[np * 2], B0[np * 2 + 1], B1[np * 2 + 1], baddr);
            }
            const uint32_t c3_0 = (uint32_t)(((ks >> 1) & 1)    ) << 7;
            const uint32_t c3_1 = (uint32_t)(((ks >> 1) & 1) ^ 1) << 7;
            const uint32_t ya   = (ks & 1) ? y01 : y00;
            const uint32_t yb   = (ks & 1) ? y11 : y10;
            #pragma unroll
            for (int mt = 0; mt < 2; ++mt) {
                const uint32_t mb = bufb + (uint32_t)mt * 4096u;
                float f0, f1;
                uint32_t a0, a1r, a2r, a3r;
                LDS64F(f0, f1, mb + ya + c3_0);              a0  = pack2(f0, f1);
                LDS64F(f0, f1, mb + 2048u + ya + c3_1);      a1r = pack2(f0, f1);
                LDS64F(f0, f1, mb + yb + c3_0);              a2r = pack2(f0, f1);
                LDS64F(f0, f1, mb + 2048u + yb + c3_1);      a3r = pack2(f0, f1);
                #pragma unroll
                for (int nt = 0; nt < 8; ++nt)
                    MMA16816(acc[mt][nt], a0, a1r, a2r, a3r, B0[nt], B1[nt]);
            }
        }
    };

    // ---- prologue: gather unit u0 (h group, then t group) ----
    if (u0 < N_UNITS) {
        int hi, ti;
        load_idx(u0, hi, ti);
        issue_g(u0, hi, Hu);
        issue_g(u0, ti, Tu);
    }

    for (int u = u0; u < N_UNITS; u += stride) {
        const int un = u + stride;
        const bool has_next = (un < N_UNITS);
        int hidx_n = 0, tidx_n = 0;
        if (has_next) load_idx(un, hidx_n, tidx_n);

        const int tile  = u >> 2;
        const int f     = u & 3;
        const int tower = tile >> 11;
        const int b     = (tile >> 1) & 1023;
        const int layer = tile & 1;

        // ---- origin slice (exact copy), overlaps in-flight gathers ----
        if (layer == 0) {
            const int oidx = (tower ? items : users)[b];
            float* outp = out + ((size_t)(tower * 3) * 1024 + b) * 256 + f * 64;
            ((float2*)outp)[lane] =
                ((const float2*)(node_emb + ((size_t)oidx * 4 + f) * 64))[lane];
        }

        float acc[2][8][4];
        #pragma unroll
        for (int mt = 0; mt < 2; ++mt)
            #pragma unroll
            for (int nt = 0; nt < 8; ++nt)
                #pragma unroll
                for (int e = 0; e < 4; ++e) acc[mt][nt][e] = 0.f;

        // ---- wait for h (groups FIFO: h is oldest; t may stay in flight) ----
        asm volatile("cp.async.wait_group 1;" ::: "memory");
        __syncwarp();

        // ---- GEMM first half: k 0..63 from H ----
        gemm_half(acc, BH, 0);

        // all H LDS consumed (in-order issue past pack2) -> H buffer dead: refill
        if (has_next) issue_g(un, hidx_n, Hu);

        // ---- wait for t (next-h stays outstanding) ----
        asm volatile("cp.async.wait_group 1;" ::: "memory");
        __syncwarp();

        // ---- GEMM second half: k 64..127 from T ----
        gemm_half(acc, BT, 64);

        // ---- logits: relu(C + b1) . W2 + b2 (b1/W2 via smem broadcast) ----
        float p[4] = {0.f, 0.f, 0.f, 0.f};
        #pragma unroll
        for (int nt = 0; nt < 8; ++nt) {
            const int n0 = nt * 8 + tc * 2;
            const float b1a = sp[n0], b1b = sp[n0 + 1];
            const float w2a = sp[64 + n0], w2b = sp[64 + n0 + 1];
            p[0] += fmaxf(acc[0][nt][0] + b1a, 0.f) * w2a + fmaxf(acc[0][nt][1] + b1b, 0.f) * w2b;
            p[1] += fmaxf(acc[0][nt][2] + b1a, 0.f) * w2a + fmaxf(acc[0][nt][3] + b1b, 0.f) * w2b;
            p[2] += fmaxf(acc[1][nt][0] + b1a, 0.f) * w2a + fmaxf(acc[1][nt][1] + b1b, 0.f) * w2b;
            p[3] += fmaxf(acc[1][nt][2] + b1a, 0.f) * w2a + fmaxf(acc[1][nt][3] + b1b, 0.f) * w2b;
        }
        float lg[4];
        #pragma unroll
        for (int e = 0; e < 4; ++e) {
            float v = p[e];
            v += __shfl_xor_sync(0xffffffffu, v, 1);
            v += __shfl_xor_sync(0xffffffffu, v, 2);
            lg[e] = v + b2v;   // rows: g, g+8, 16+g, 24+g
        }

        // ---- softmax over the warp's 32 rows ----
        float m = fmaxf(fmaxf(lg[0], lg[1]), fmaxf(lg[2], lg[3]));
        #pragma unroll
        for (int o = 4; o <= 16; o <<= 1)
            m = fmaxf(m, __shfl_xor_sync(0xffffffffu, m, o));
        float e0 = __expf(lg[0] - m), e1 = __expf(lg[1] - m);
        float e2 = __expf(lg[2] - m), e3 = __expf(lg[3] - m);
        float s = e0 + e1 + e2 + e3;
        #pragma unroll
        for (int o = 4; o <= 16; o <<= 1)
            s += __shfl_xor_sync(0xffffffffu, s, o);
        const float rs = __frcp_rn(s);
        if (tc == 0) {
            swgt[g]      = e0 * rs;
            swgt[g + 8]  = e1 * rs;
            swgt[g + 16] = e2 * rs;
            swgt[g + 24] = e3 * rs;
        }
        __syncwarp();

        // ---- weighted sum of exact fp32 t over k; dims d = 2*lane, 2*lane+1 ----
        {
            const int slot = lane >> 1;          // (2*lane)>>2
            const int off  = (lane & 1) << 1;    // 0 or 2
            float a0 = 0.f, a1 = 0.f;
            #pragma unroll
            for (int r4 = 0; r4 < 8; ++r4) {
                const float4 w4 = swgt4[r4];
                #pragma unroll
                for (int j = 0; j < 4; ++j) {
                    const int rr = r4 * 4 + j;
                    const float w = (j == 0) ? w4.x : (j == 1) ? w4.y : (j == 2) ? w4.z : w4.w;
                    const float2 tv = *(const float2*)&stw[rr * 64 + ((slot ^ (rr & 15)) << 2) + off];
                    a0 += w * tv.x;
                    a1 += w * tv.y;
                }
            }
            float* outp = out + (((size_t)(tower * 3 + 1 + layer)) * 1024 + b) * 256 + f * 64;
            *(float2*)(outp + 2 * lane) = make_float2(a0, a1);
        }
        __syncwarp();

        // ---- T buffer dead (wsum stored): refill for next unit ----
        if (has_next) issue_g(un, tidx_n, Tu);
    }
}

extern "C" void kernel_launch(void* const* d_in, const int* in_sizes, int n_in,
                              void* d_out, int out_size)
{
    const float* node_emb = (const float*)d_in[0];
    // d_in[1] = relation_emb: unused by the reference computation
    const float* W1    = (const float*)d_in[2];
    const float* b1    = (const float*)d_in[3];
    const float* W2    = (const float*)d_in[4];
    const float* b2    = (const float*)d_in[5];
    const int*   users = (const int*)d_in[6];
    const int*   items = (const int*)d_in[7];
    const int*   utri  = (const int*)d_in[8];
    const int*   itri  = (const int*)d_in[9];
    float*       out   = (float*)d_out;

    int nsm = 148;
    cudaDeviceGetAttribute(&nsm, cudaDevAttrMultiProcessorCount, 0);

    cudaFuncSetAttribute(kgat_split_kernel,
                         cudaFuncAttributeMaxDynamicSharedMemorySize, SMEM_BYTES);
    kgat_split_kernel<<<nsm, THREADS, SMEM_BYTES>>>(
        node_emb, W1, b1, W2, b2, users, items, utri, itri, out);
}